// round 3
// baseline (speedup 1.0000x reference)
#include <cuda_runtime.h>

// Scratch: split-K partials [8][512*256] and x3 [512 x 64].
static __device__ float g_part[8][512 * 256];
static __device__ float g_x3[512 * 64];

// ---------------------------------------------------------------------------
// Kernel A1: split-K partial GEMM.  part[z] = x[64r x 64k] @ w2^T[64k x 64h]
// grid (8 rowTiles, 4 hidTiles, 8 kSplits) = 256 blocks, 256 threads,
// 4x4 register tiles, single load phase per block.
// ---------------------------------------------------------------------------
__global__ void __launch_bounds__(256) gemm1_part_kernel(
    const float* __restrict__ x,    // [512, 512]
    const float* __restrict__ w2)   // [256, 512]
{
    __shared__ float xs[64][68];
    __shared__ float ws[64][68];

    const int t  = threadIdx.x;
    const int r0 = blockIdx.x * 64;
    const int h0 = blockIdx.y * 64;
    const int k0 = blockIdx.z * 64;
    const int tx = t & 15;          // col group
    const int ty = t >> 4;          // row group

    // cooperative coalesced load: 64 rows x 64 k (16 float4 per row) per tile
    #pragma unroll
    for (int i = 0; i < 4; ++i) {
        const int idx = t + i * 256;
        const int r  = idx >> 4;
        const int kq = idx & 15;
        float4 vx = *reinterpret_cast<const float4*>(
            x + (size_t)(r0 + r) * 512 + k0 + kq * 4);
        *reinterpret_cast<float4*>(&xs[r][kq * 4]) = vx;
        float4 vw = *reinterpret_cast<const float4*>(
            w2 + (size_t)(h0 + r) * 512 + k0 + kq * 4);
        *reinterpret_cast<float4*>(&ws[r][kq * 4]) = vw;
    }

    float acc[4][4];
    #pragma unroll
    for (int i = 0; i < 4; ++i)
        #pragma unroll
        for (int j = 0; j < 4; ++j) acc[i][j] = 0.f;

    __syncthreads();

    #pragma unroll 4
    for (int kq = 0; kq < 64; kq += 4) {
        float4 a[4], bv[4];
        #pragma unroll
        for (int i = 0; i < 4; ++i)
            a[i] = *reinterpret_cast<const float4*>(&xs[ty * 4 + i][kq]);
        #pragma unroll
        for (int j = 0; j < 4; ++j)
            bv[j] = *reinterpret_cast<const float4*>(&ws[tx * 4 + j][kq]);
        #pragma unroll
        for (int i = 0; i < 4; ++i)
            #pragma unroll
            for (int j = 0; j < 4; ++j) {
                acc[i][j] = fmaf(a[i].x, bv[j].x, acc[i][j]);
                acc[i][j] = fmaf(a[i].y, bv[j].y, acc[i][j]);
                acc[i][j] = fmaf(a[i].z, bv[j].z, acc[i][j]);
                acc[i][j] = fmaf(a[i].w, bv[j].w, acc[i][j]);
            }
    }

    float* dst = g_part[blockIdx.z];
    #pragma unroll
    for (int i = 0; i < 4; ++i) {
        float4 v = make_float4(acc[i][0], acc[i][1], acc[i][2], acc[i][3]);
        *reinterpret_cast<float4*>(
            dst + (size_t)(r0 + ty * 4 + i) * 256 + h0 + tx * 4) = v;
    }
}

// ---------------------------------------------------------------------------
// Kernel A2: reduce 8 partials + bias + LeakyReLU, GEMM2 + softmaxes -> x3.
// One block per 4 batch rows, 256 threads, grid 128.
// ---------------------------------------------------------------------------
__global__ void __launch_bounds__(256) head_kernel(
    const float* __restrict__ b2,   // [256]
    const float* __restrict__ w3,   // [55, 256]
    const float* __restrict__ b3)   // [55]
{
    __shared__ float hs[4][256];
    __shared__ float zs[4][60];

    const int t  = threadIdx.x;
    const int r0 = blockIdx.x * 4;

    const float bb = b2[t];
    #pragma unroll
    for (int i = 0; i < 4; ++i) {
        const size_t off = (size_t)(r0 + i) * 256 + t;
        float s = bb;
        #pragma unroll
        for (int z = 0; z < 8; ++z) s += g_part[z][off];
        hs[i][t] = (s >= 0.f) ? s : 0.01f * s;
    }
    __syncthreads();

    if (t < 220) {
        const int r = t / 55;
        const int c = t - 55 * r;
        const float4* hv = reinterpret_cast<const float4*>(hs[r]);
        const float4* wv = reinterpret_cast<const float4*>(w3 + (size_t)c * 256);
        float acc = 0.f;
        #pragma unroll 8
        for (int k = 0; k < 64; ++k) {
            const float4 a = hv[k];
            const float4 w = __ldg(&wv[k]);
            acc = fmaf(a.x, w.x, acc); acc = fmaf(a.y, w.y, acc);
            acc = fmaf(a.z, w.z, acc); acc = fmaf(a.w, w.w, acc);
        }
        zs[r][c] = acc + b3[c];
    }
    __syncthreads();

    if (t < 24) {
        const int r     = t / 6;
        const int g     = t - 6 * r;
        const int start = (g == 0) ? 0 : 5 + 10 * (g - 1);
        const int len   = (g == 0) ? 5 : 10;
        float m = -3.0e38f;
        for (int c = 0; c < len; ++c) m = fmaxf(m, zs[r][start + c]);
        float s = 0.f;
        for (int c = 0; c < len; ++c) s += __expf(zs[r][start + c] - m);
        const float inv = 1.0f / s;
        float* dst = &g_x3[(size_t)(r0 + r) * 64];
        for (int c = 0; c < len; ++c)
            dst[start + c] = __expf(zs[r][start + c] - m) * inv;
    }
}

// ---------------------------------------------------------------------------
// Kernel B: expansion via aligned 20-float chunks (= 5 float4 = 2 runs).
//
// Row b starts at abs offset b*99999; 99999 == 3 (mod 4) => first 16B-aligned
// index in the row is pad = b & 3. Chunks start at i = pad + 20*c, and since
// 20 == 0 (mod 10) the run-phase phi = i mod 10 = pad is CONSTANT per row.
// Chunk c covers runs {2c, 2c+1, (2c+2 iff pad>0)}; store pattern is one of
// 4 fixed select-free layouts chosen by a block-uniform switch on pad.
//
// nchunks per row = 4999 (covers [pad, pad+99980)); head = pad scalars,
// tail = 19-pad scalars. Specials: i=0 -> p[1]*p[5]; run 0 -> p[0].
// grid (20, 512), 256 threads, 1 chunk per thread.
// ---------------------------------------------------------------------------
__global__ void __launch_bounds__(256) expand_kernel(float* __restrict__ out)
{
    __shared__ float p[64];
    __shared__ float sv[513];

    const unsigned t   = threadIdx.x;
    const unsigned bx  = blockIdx.x;
    const unsigned b   = blockIdx.y;
    const unsigned pad = b & 3u;
    const unsigned C0  = bx * 256u;       // first chunk of this block

    if (t < 64u) p[t] = g_x3[(size_t)b * 64u + t];
    __syncthreads();

    // --- phase 1: run values for runs [2*C0, 2*C0 + 512] ---
    const unsigned rbase = 2u * C0;
    #pragma unroll
    for (unsigned k = 0; k < 3u; ++k) {
        const unsigned ri = t + k * 256u;
        if (ri < 513u) {
            const unsigned r = rbase + ri;
            float v = 0.f;
            if (r < 10000u) {
                if (r == 0u) {
                    v = p[0];
                } else if (r < 10u) {
                    v = p[1] * p[5 + r];
                } else if (r < 100u) {
                    const unsigned q1 = r / 10u;
                    v = p[2] * p[5 + q1] * p[15 + (r - 10u * q1)];
                } else if (r < 1000u) {
                    const unsigned q1 = r / 10u, q2 = r / 100u;
                    v = p[3] * p[5 + q2] * p[15 + (q1 - 10u * q2)]
                             * p[25 + (r - 10u * q1)];
                } else {
                    const unsigned q1 = r / 10u, q2 = r / 100u, q3 = r / 1000u;
                    v = p[4] * p[5 + q3] * p[15 + (q2 - 10u * q3)]
                             * p[25 + (q1 - 10u * q2)] * p[35 + (r - 10u * q1)];
                }
            }
            sv[ri] = v;
        }
    }
    __syncthreads();

    float* o = out + (size_t)b * 99999u;

    // --- phase 2: one 20-float chunk per thread, 5 aligned float4 stores ---
    const unsigned c = C0 + t;
    if (c < 4999u) {
        const float f0 = sv[2u * t];
        const float f1 = sv[2u * t + 1u];
        const float f2 = sv[2u * t + 2u];
        float4* dst = reinterpret_cast<float4*>(o + pad + 20u * c);
        const float4 F0 = make_float4(f0, f0, f0, f0);
        const float4 F1 = make_float4(f1, f1, f1, f1);
        switch (pad) {           // block-uniform
        case 0u:
            dst[0] = F0; dst[1] = F0;
            dst[2] = make_float4(f0, f0, f1, f1);
            dst[3] = F1; dst[4] = F1;
            break;
        case 1u:
            dst[0] = F0; dst[1] = F0;
            dst[2] = make_float4(f0, f1, f1, f1);
            dst[3] = F1;
            dst[4] = make_float4(f1, f1, f1, f2);
            break;
        case 2u:
            dst[0] = F0; dst[1] = F0;
            dst[2] = F1; dst[3] = F1;
            dst[4] = make_float4(f1, f1, f2, f2);
            break;
        default:
            dst[0] = F0;
            dst[1] = make_float4(f0, f0, f0, f1);
            dst[2] = F1; dst[3] = F1;
            dst[4] = make_float4(f1, f2, f2, f2);
            break;
        }
        // patch out[b, 0]: chunk 0 of pad==0 rows overwrote it with p[0]
        if (c == 0u && pad == 0u) o[0] = p[1] * p[5];
    }

    // --- head: i in [0, pad) ---
    if (bx == 0u && t < pad) {
        o[t] = (t == 0u) ? p[1] * p[5] : p[0];
    }

    // --- tail: i in [pad+99980, 99999), runs 9998/9999 (sv idx - 9728) ---
    if (bx == 19u && t < 19u - pad) {
        const unsigned i = pad + 99980u + t;
        o[i] = sv[i / 10u - 9728u];
    }
}

// ---------------------------------------------------------------------------
extern "C" void kernel_launch(void* const* d_in, const int* in_sizes, int n_in,
                              void* d_out, int out_size)
{
    (void)in_sizes; (void)n_in; (void)out_size;
    const float* x  = (const float*)d_in[0];   // [512, 512]
    const float* w2 = (const float*)d_in[1];   // [256, 512]
    const float* b2 = (const float*)d_in[2];   // [256]
    const float* w3 = (const float*)d_in[3];   // [55, 256]
    const float* b3 = (const float*)d_in[4];   // [55]
    float* out = (float*)d_out;                // [512, 99999]

    gemm1_part_kernel<<<dim3(8, 4, 8), 256>>>(x, w2);
    head_kernel<<<128, 256>>>(b2, w3, b3);
    expand_kernel<<<dim3(20, 512), 256>>>(out);
}

// round 4
// speedup vs baseline: 2.2536x; 2.2536x over previous
#include <cuda_runtime.h>

// Scratch: split-K partials [16][512*256] (8 MB) and x3 [512 x 64].
static __device__ float g_part[16][512 * 256];
static __device__ float g_x3[512 * 64];

// ---------------------------------------------------------------------------
// Kernel A1: split-K partial GEMM.  part[z] = x[64r x 32k] @ w2^T[32k x 64h]
// grid (8 rowTiles, 4 hidTiles, 16 kSplits) = 512 blocks, 256 threads.
// 4x4 register tiles with 16-strided rows/cols (conflict-free LDS.128).
// ---------------------------------------------------------------------------
__global__ void __launch_bounds__(256) gemm1_part_kernel(
    const float* __restrict__ x,    // [512, 512]
    const float* __restrict__ w2)   // [256, 512]
{
    __shared__ float xs[64][36];
    __shared__ float ws[64][36];

    const int t  = threadIdx.x;
    const int r0 = blockIdx.x * 64;
    const int h0 = blockIdx.y * 64;
    const int k0 = blockIdx.z * 32;

    // load 64x32 of x and w2 (2 float4 per thread each)
    #pragma unroll
    for (int i = 0; i < 2; ++i) {
        const int idx = t + i * 256;     // 0..511
        const int r   = idx >> 3;        // row 0..63
        const int kq  = (idx & 7) * 4;   // 0..28
        float4 vx = *reinterpret_cast<const float4*>(
            x + (size_t)(r0 + r) * 512 + k0 + kq);
        *reinterpret_cast<float4*>(&xs[r][kq]) = vx;
        float4 vw = *reinterpret_cast<const float4*>(
            w2 + (size_t)(h0 + r) * 512 + k0 + kq);
        *reinterpret_cast<float4*>(&ws[r][kq]) = vw;
    }

    float acc[4][4];
    #pragma unroll
    for (int i = 0; i < 4; ++i)
        #pragma unroll
        for (int j = 0; j < 4; ++j) acc[i][j] = 0.f;

    const int tx = t & 15;   // col base (cols tx, tx+16, tx+32, tx+48)
    const int ty = t >> 4;   // row base (rows ty, ty+16, ty+32, ty+48)

    __syncthreads();

    #pragma unroll
    for (int kq = 0; kq < 32; kq += 4) {
        float4 a[4], bv[4];
        #pragma unroll
        for (int i = 0; i < 4; ++i)
            a[i] = *reinterpret_cast<const float4*>(&xs[ty + 16 * i][kq]);
        #pragma unroll
        for (int j = 0; j < 4; ++j)
            bv[j] = *reinterpret_cast<const float4*>(&ws[tx + 16 * j][kq]);
        #pragma unroll
        for (int i = 0; i < 4; ++i)
            #pragma unroll
            for (int j = 0; j < 4; ++j) {
                acc[i][j] = fmaf(a[i].x, bv[j].x, acc[i][j]);
                acc[i][j] = fmaf(a[i].y, bv[j].y, acc[i][j]);
                acc[i][j] = fmaf(a[i].z, bv[j].z, acc[i][j]);
                acc[i][j] = fmaf(a[i].w, bv[j].w, acc[i][j]);
            }
    }

    float* dst = g_part[blockIdx.z];
    #pragma unroll
    for (int i = 0; i < 4; ++i)
        #pragma unroll
        for (int j = 0; j < 4; ++j)
            dst[(size_t)(r0 + ty + 16 * i) * 256 + h0 + tx + 16 * j] = acc[i][j];
}

// ---------------------------------------------------------------------------
// Kernel A2: reduce 16 partials + bias + LeakyReLU, GEMM2 + softmaxes -> x3.
// One block per 4 batch rows, 256 threads, grid 128.
// ---------------------------------------------------------------------------
__global__ void __launch_bounds__(256) head_kernel(
    const float* __restrict__ b2,   // [256]
    const float* __restrict__ w3,   // [55, 256]
    const float* __restrict__ b3)   // [55]
{
    __shared__ float hs[4][256];
    __shared__ float zs[4][60];

    const int t  = threadIdx.x;
    const int r0 = blockIdx.x * 4;

    const float bb = b2[t];
    #pragma unroll
    for (int i = 0; i < 4; ++i) {
        const size_t off = (size_t)(r0 + i) * 256 + t;
        float s = bb;
        #pragma unroll
        for (int z = 0; z < 16; ++z) s += g_part[z][off];
        hs[i][t] = (s >= 0.f) ? s : 0.01f * s;
    }
    __syncthreads();

    if (t < 220) {
        const int r = t / 55;
        const int c = t - 55 * r;
        const float4* hv = reinterpret_cast<const float4*>(hs[r]);
        const float4* wv = reinterpret_cast<const float4*>(w3 + (size_t)c * 256);
        float acc = 0.f;
        #pragma unroll 8
        for (int k = 0; k < 64; ++k) {
            const float4 a = hv[k];
            const float4 w = __ldg(&wv[k]);
            acc = fmaf(a.x, w.x, acc); acc = fmaf(a.y, w.y, acc);
            acc = fmaf(a.z, w.z, acc); acc = fmaf(a.w, w.w, acc);
        }
        zs[r][c] = acc + b3[c];
    }
    __syncthreads();

    if (t < 24) {
        const int r     = t / 6;
        const int g     = t - 6 * r;
        const int start = (g == 0) ? 0 : 5 + 10 * (g - 1);
        const int len   = (g == 0) ? 5 : 10;
        float m = -3.0e38f;
        for (int c = 0; c < len; ++c) m = fmaxf(m, zs[r][start + c]);
        float s = 0.f;
        for (int c = 0; c < len; ++c) s += __expf(zs[r][start + c] - m);
        const float inv = 1.0f / s;
        float* dst = &g_x3[(size_t)(r0 + r) * 64];
        for (int c = 0; c < len; ++c)
            dst[start + c] = __expf(zs[r][start + c] - m) * inv;
    }
}

// ---------------------------------------------------------------------------
// Kernel B: expansion.  out[b, i] constant over runs of 10 (r = i/10).
//
// Lane-contiguous float4 stores (full coalescing). 320 threads => one block
// iteration covers 320 float4 = 1280 floats == 0 (mod 10), so each thread's
// run-phase rem = (pad + 4t) mod 10 and base run rt = (pad + 4t)/10 are
// LOOP-INVARIANT; sv index just increments by 128 per iteration.
//
// Row b: pad = b & 3 scalar head floats, then 24999 aligned float4, then
// (3 - pad) scalar tail floats. grid (14, 512): bx<13 full (6 iters x 320),
// bx==13 does the guarded remainder (39 float4) + tail.
// ---------------------------------------------------------------------------
__global__ void __launch_bounds__(320) expand_kernel(float* __restrict__ out)
{
    __shared__ float p[64];
    __shared__ float sv[772];

    const unsigned t   = threadIdx.x;
    const unsigned bx  = blockIdx.x;
    const unsigned b   = blockIdx.y;
    const unsigned pad = b & 3u;

    if (t < 64u) p[t] = g_x3[(size_t)b * 64u + t];
    __syncthreads();

    // --- phase 1: run values for runs [bx*768, bx*768 + 769] ---
    const unsigned rbase = bx * 768u;
    #pragma unroll
    for (unsigned kk = 0; kk < 3u; ++kk) {
        const unsigned ri = t + kk * 320u;
        if (ri < 770u) {
            const unsigned r = rbase + ri;
            float v = 0.f;
            if (r < 10000u) {
                if (r == 0u) {
                    v = p[0];
                } else if (r < 10u) {
                    v = p[1] * p[5 + r];
                } else if (r < 100u) {
                    const unsigned q1 = r / 10u;
                    v = p[2] * p[5 + q1] * p[15 + (r - 10u * q1)];
                } else if (r < 1000u) {
                    const unsigned q1 = r / 10u, q2 = r / 100u;
                    v = p[3] * p[5 + q2] * p[15 + (q1 - 10u * q2)]
                             * p[25 + (r - 10u * q1)];
                } else {
                    const unsigned q1 = r / 10u, q2 = r / 100u, q3 = r / 1000u;
                    v = p[4] * p[5 + q3] * p[15 + (q2 - 10u * q3)]
                             * p[25 + (q1 - 10u * q2)] * p[35 + (r - 10u * q1)];
                }
            }
            sv[ri] = v;
        }
    }
    __syncthreads();

    float* o = out + (size_t)b * 99999u;
    float4* ov = reinterpret_cast<float4*>(o + pad);   // 16B-aligned

    // loop-invariant per-thread phase
    const unsigned ph  = pad + 4u * t;       // < 1283
    const unsigned rt  = ph / 10u;
    const unsigned rem = ph - 10u * rt;
    const bool c1 = (rem + 1u < 10u);
    const bool c2 = (rem + 2u < 10u);
    const bool c3 = (rem + 3u < 10u);

    if (bx < 13u) {
        // full blocks: 6 unguarded iterations
        unsigned vi = bx * 1920u + t;
        unsigned ri = rt;
        #pragma unroll
        for (int k = 0; k < 6; ++k) {
            const float f0 = sv[ri];
            const float f1 = sv[ri + 1u];
            float4 w;
            w.x = f0;
            w.y = c1 ? f0 : f1;
            w.z = c2 ? f0 : f1;
            w.w = c3 ? f0 : f1;
            ov[vi] = w;
            vi += 320u;
            ri += 128u;
        }
        // head + patch out[b, 0]
        if (bx == 0u && t < 4u) {
            if (t == 0u) o[0] = p[1] * p[5];
            else if (t < pad) o[t] = p[0];
        }
    } else {
        // remainder block: float4 [24960, 24999)
        const unsigned vi = 24960u + t;
        if (vi < 24999u) {
            const float f0 = sv[rt];
            const float f1 = sv[rt + 1u];
            float4 w;
            w.x = f0;
            w.y = c1 ? f0 : f1;
            w.z = c2 ? f0 : f1;
            w.w = c3 ? f0 : f1;
            ov[vi] = w;
        }
        // scalar tail: i in [pad + 99996, 99999)  (all run 9999 -> sv[15])
        if (t < 3u - pad) {
            o[pad + 99996u + t] = sv[15];
        }
    }
}

// ---------------------------------------------------------------------------
extern "C" void kernel_launch(void* const* d_in, const int* in_sizes, int n_in,
                              void* d_out, int out_size)
{
    (void)in_sizes; (void)n_in; (void)out_size;
    const float* x  = (const float*)d_in[0];   // [512, 512]
    const float* w2 = (const float*)d_in[1];   // [256, 512]
    const float* b2 = (const float*)d_in[2];   // [256]
    const float* w3 = (const float*)d_in[3];   // [55, 256]
    const float* b3 = (const float*)d_in[4];   // [55]
    float* out = (float*)d_out;                // [512, 99999]

    gemm1_part_kernel<<<dim3(8, 4, 16), 256>>>(x, w2);
    head_kernel<<<128, 256>>>(b2, w3, b3);
    expand_kernel<<<dim3(14, 512), 320>>>(out);
}